// round 7
// baseline (speedup 1.0000x reference)
#include <cuda_runtime.h>
#include <cuda_bf16.h>
#include <math.h>
#include <stdint.h>

constexpr int B_  = 32;
constexpr int TD  = 64;
constexpr int TE  = 256;
constexpr int H_  = 512;
constexpr int E_  = 512;
constexpr int V_  = 32000;
constexpr int L_  = 2;
constexpr int NH  = 8;
constexpr int DH  = 64;
constexpr int BTV = B_ * TD * V_;
constexpr int LBH = L_ * B_ * H_;

constexpr int NBLK = 128;
constexpr int NTHR = 512;

// ---------------- scratch (device globals) ----------------------------------
__device__ __align__(16) float g_Kh  [B_ * TE * H_];
__device__ __align__(16) float g_Kh2 [B_ * NH * DH * TE];
__device__ __align__(16) float g_Vh  [B_ * TE * H_];
__device__ __align__(16) float g_eproj[TD * B_ * H_];
__device__ __align__(16) float g_Wcombt[H_ * H_];
__device__ __align__(16) float g_hA[LBH];
__device__ __align__(16) float g_hB[LBH];
__device__ __align__(16) float g_ctx[B_ * H_];
__device__ __align__(16) float g_xra[B_ * H_];
__device__ __align__(16) float g_xrb[B_ * H_];
__device__ int g_bar;

__device__ __align__(16) __nv_bfloat16 g_enc_h [B_ * TE * 2 * H_];
__device__ __align__(16) __nv_bfloat16 g_enc_l [B_ * TE * 2 * H_];
__device__ __align__(16) __nv_bfloat16 g_Wkt_h [H_ * 2 * H_];
__device__ __align__(16) __nv_bfloat16 g_Wkt_l [H_ * 2 * H_];
__device__ __align__(16) __nv_bfloat16 g_Wvt_h [H_ * 2 * H_];
__device__ __align__(16) __nv_bfloat16 g_Wvt_l [H_ * 2 * H_];
__device__ __align__(16) __nv_bfloat16 g_Wint_h[H_ * H_];
__device__ __align__(16) __nv_bfloat16 g_Wint_l[H_ * H_];
__device__ __align__(16) __nv_bfloat16 g_Wdt_h [V_ * H_];
__device__ __align__(16) __nv_bfloat16 g_Wdt_l [V_ * H_];
__device__ __align__(16) __nv_bfloat16 g_eseq_h[TD * B_ * E_];
__device__ __align__(16) __nv_bfloat16 g_eseq_l[TD * B_ * E_];
__device__ __align__(16) __nv_bfloat16 g_ys_h  [TD * B_ * H_];
__device__ __align__(16) __nv_bfloat16 g_ys_l  [TD * B_ * H_];

// ======================= helpers =============================================
__device__ __forceinline__ uint32_t smem_u32(const void* p) {
    uint32_t a;
    asm("{ .reg .u64 t; cvta.to.shared.u64 t, %1; cvt.u32.u64 %0, t; }"
        : "=r"(a) : "l"(p));
    return a;
}
__device__ __forceinline__ void ldsm4(uint32_t (&r)[4], uint32_t addr) {
    asm volatile("ldmatrix.sync.aligned.m8n8.x4.shared.b16 {%0,%1,%2,%3}, [%4];"
        : "=r"(r[0]), "=r"(r[1]), "=r"(r[2]), "=r"(r[3]) : "r"(addr));
}
__device__ __forceinline__ void mma16816(float (&d)[4], const uint32_t (&a)[4],
                                         uint32_t b0, uint32_t b1) {
    asm volatile(
        "mma.sync.aligned.m16n8k16.row.col.f32.bf16.bf16.f32 "
        "{%0,%1,%2,%3}, {%4,%5,%6,%7}, {%8,%9}, {%0,%1,%2,%3};"
        : "+f"(d[0]), "+f"(d[1]), "+f"(d[2]), "+f"(d[3])
        : "r"(a[0]), "r"(a[1]), "r"(a[2]), "r"(a[3]), "r"(b0), "r"(b1));
}
__device__ __forceinline__ float fsig(float x) {
    return 1.f / (1.f + __expf(-x));
}
__device__ __forceinline__ float ftanh(float x) {
    return 2.f / (1.f + __expf(-2.f * x)) - 1.f;
}
__device__ __forceinline__ void bsplit(float x, __nv_bfloat16& h, __nv_bfloat16& l) {
    h = __float2bfloat16(x);
    l = __float2bfloat16(x - __bfloat162float(h));
}

// ============ HMMA compensated-bf16 GEMM body (pipelined) ====================
constexpr int BKg  = 32;
constexpr int LDSg = BKg + 8;

__device__ __forceinline__ void mma_gemm_body(
    __nv_bfloat16* sAh, __nv_bfloat16* sAl, __nv_bfloat16* sBh, __nv_bfloat16* sBl,
    int M, int N, int K,
    const __nv_bfloat16* __restrict__ Ah, const __nv_bfloat16* __restrict__ Al,
    const __nv_bfloat16* __restrict__ Bh, const __nv_bfloat16* __restrict__ Bl,
    float* __restrict__ C, const float* __restrict__ bias, int mode,
    int bx, int by)
{
    const int tid = threadIdx.x, lane = tid & 31, wid = tid >> 5;
    const int wm = wid >> 1, wn = wid & 1;
    const int n0 = bx * 128, m0 = by * 128;

    float acc[2][8][4];
#pragma unroll
    for (int i = 0; i < 2; i++)
#pragma unroll
        for (int j = 0; j < 8; j++)
#pragma unroll
            for (int k = 0; k < 4; k++) acc[i][j][k] = 0.f;

    const int lrow = tid >> 2;
    const int lcol = (tid & 3) * 8;

    uint4 rAh[2], rAl[2], rBh[2], rBl[2];
#pragma unroll
    for (int h = 0; h < 2; h++) {
        int row = lrow + h * 64;
        size_t ga = (size_t)(m0 + row) * K + lcol;
        size_t gb = (size_t)(n0 + row) * K + lcol;
        rAh[h] = *(const uint4*)(Ah + ga);
        rAl[h] = *(const uint4*)(Al + ga);
        rBh[h] = *(const uint4*)(Bh + gb);
        rBl[h] = *(const uint4*)(Bl + gb);
    }

    const int nchunks = K >> 5;
    for (int kc = 0; kc < nchunks; kc++) {
        __syncthreads();
#pragma unroll
        for (int h = 0; h < 2; h++) {
            int row = lrow + h * 64;
            uint32_t so = row * LDSg + lcol;
            *(uint4*)&sAh[so] = rAh[h];
            *(uint4*)&sAl[so] = rAl[h];
            *(uint4*)&sBh[so] = rBh[h];
            *(uint4*)&sBl[so] = rBl[h];
        }
        __syncthreads();
        if (kc + 1 < nchunks) {
            int kb = (kc + 1) << 5;
#pragma unroll
            for (int h = 0; h < 2; h++) {
                int row = lrow + h * 64;
                size_t ga = (size_t)(m0 + row) * K + kb + lcol;
                size_t gb = (size_t)(n0 + row) * K + kb + lcol;
                rAh[h] = *(const uint4*)(Ah + ga);
                rAl[h] = *(const uint4*)(Al + ga);
                rBh[h] = *(const uint4*)(Bh + gb);
                rBl[h] = *(const uint4*)(Bl + gb);
            }
        }

#pragma unroll
        for (int ks = 0; ks < BKg; ks += 16) {
            uint32_t ah[2][4], al[2][4];
            const uint32_t fcol = ks + (lane >> 4) * 8;
#pragma unroll
            for (int mi = 0; mi < 2; mi++) {
                uint32_t arow = wm * 32 + mi * 16 + (lane & 15);
                ldsm4(ah[mi], smem_u32(&sAh[arow * LDSg + fcol]));
                ldsm4(al[mi], smem_u32(&sAl[arow * LDSg + fcol]));
            }
#pragma unroll
            for (int nj = 0; nj < 4; nj++) {
                uint32_t brow = wn * 64 + nj * 16 + (lane & 15);
                uint32_t bh[4], bl[4];
                ldsm4(bh, smem_u32(&sBh[brow * LDSg + fcol]));
                ldsm4(bl, smem_u32(&sBl[brow * LDSg + fcol]));
#pragma unroll
                for (int mi = 0; mi < 2; mi++) {
                    mma16816(acc[mi][2 * nj],     ah[mi], bh[0], bh[2]);
                    mma16816(acc[mi][2 * nj + 1], ah[mi], bh[1], bh[3]);
                    mma16816(acc[mi][2 * nj],     ah[mi], bl[0], bl[2]);
                    mma16816(acc[mi][2 * nj + 1], ah[mi], bl[1], bl[3]);
                    mma16816(acc[mi][2 * nj],     al[mi], bh[0], bh[2]);
                    mma16816(acc[mi][2 * nj + 1], al[mi], bh[1], bh[3]);
                }
            }
        }
    }

#pragma unroll
    for (int mi = 0; mi < 2; mi++) {
        int row = m0 + wm * 32 + mi * 16 + (lane >> 2);
#pragma unroll
        for (int nt = 0; nt < 8; nt++) {
            int col = n0 + wn * 64 + nt * 8 + (lane & 3) * 2;
            float bb0 = bias ? bias[col] : 0.f;
            float bb1 = bias ? bias[col + 1] : 0.f;
            float2 v0 = make_float2(acc[mi][nt][0] + bb0, acc[mi][nt][1] + bb1);
            float2 v1 = make_float2(acc[mi][nt][2] + bb0, acc[mi][nt][3] + bb1);
            if (mode == 0) {
                *(float2*)&C[(size_t)row * N + col] = v0;
                *(float2*)&C[(size_t)(row + 8) * N + col] = v1;
            } else {
                int t0 = row >> 5, b0v_ = row & 31;
                int t1 = (row + 8) >> 5, b1v_ = (row + 8) & 31;
                *(float2*)&C[(size_t)b0v_ * (TD * V_) + (size_t)t0 * V_ + col] = v0;
                *(float2*)&C[(size_t)b1v_ * (TD * V_) + (size_t)t1 * V_ + col] = v1;
            }
        }
    }
}

__global__ __launch_bounds__(256, 2) void mma_gemm_kernel(
    int M, int N, int K,
    const __nv_bfloat16* __restrict__ Ah, const __nv_bfloat16* __restrict__ Al,
    const __nv_bfloat16* __restrict__ Bh, const __nv_bfloat16* __restrict__ Bl,
    float* __restrict__ C, const float* __restrict__ bias, int mode)
{
    __shared__ __nv_bfloat16 sAh[128 * LDSg], sAl[128 * LDSg];
    __shared__ __nv_bfloat16 sBh[128 * LDSg], sBl[128 * LDSg];
    mma_gemm_body(sAh, sAl, sBh, sBl, M, N, K, Ah, Al, Bh, Bl, C, bias, mode,
                  blockIdx.x, blockIdx.y);
}

// batched K/V/eproj projections in one launch (z selects)
__global__ __launch_bounds__(256, 2) void mma_batched_kernel(
    const __nv_bfloat16* __restrict__ encH, const __nv_bfloat16* __restrict__ encL,
    const __nv_bfloat16* __restrict__ WkH,  const __nv_bfloat16* __restrict__ WkL,
    const __nv_bfloat16* __restrict__ WvH,  const __nv_bfloat16* __restrict__ WvL,
    const __nv_bfloat16* __restrict__ esH,  const __nv_bfloat16* __restrict__ esL,
    const __nv_bfloat16* __restrict__ WinH, const __nv_bfloat16* __restrict__ WinL,
    float* __restrict__ Kh, float* __restrict__ Vh, float* __restrict__ eproj)
{
    __shared__ __nv_bfloat16 sAh[128 * LDSg], sAl[128 * LDSg];
    __shared__ __nv_bfloat16 sBh[128 * LDSg], sBl[128 * LDSg];
    int z = blockIdx.z;
    if (z == 0) {
        mma_gemm_body(sAh, sAl, sBh, sBl, B_ * TE, H_, 2 * H_,
                      encH, encL, WkH, WkL, Kh, nullptr, 0, blockIdx.x, blockIdx.y);
    } else if (z == 1) {
        mma_gemm_body(sAh, sAl, sBh, sBl, B_ * TE, H_, 2 * H_,
                      encH, encL, WvH, WvL, Vh, nullptr, 0, blockIdx.x, blockIdx.y);
    } else {
        if (blockIdx.y >= (TD * B_) / 128) return;   // 32 y-blocks for eproj
        mma_gemm_body(sAh, sAl, sBh, sBl, TD * B_, H_, E_,
                      esH, esL, WinH, WinL, eproj, nullptr, 0, blockIdx.x, blockIdx.y);
    }
}

// ---------------- fused prep: conversions + gather + h copy -----------------
__device__ void tconv_body(const float* __restrict__ W, int K, int N, int row_off,
                           __nv_bfloat16* __restrict__ oh, __nv_bfloat16* __restrict__ ol,
                           int bxx, int byy, float* t /*32*33 smem*/)
{
    int tx = threadIdx.x & 31, ty = threadIdx.x >> 5;
    int n0 = bxx * 32, k0 = byy * 32;
    for (int ky = ty; ky < 32; ky += 8)
        t[ky * 33 + tx] = W[(size_t)(row_off + k0 + ky) * N + n0 + tx];
    __syncthreads();
    for (int ny = ty; ny < 32; ny += 8) {
        float v = t[tx * 33 + ny];
        __nv_bfloat16 h, l; bsplit(v, h, l);
        size_t o = (size_t)(n0 + ny) * K + k0 + tx;
        oh[o] = h; ol[o] = l;
    }
}

constexpr int SEG0 = (B_ * TE * 2 * H_) / 4 / 256;   // 8192: aconv enc (float4)
constexpr int SEG1 = SEG0 + 512;     // tconv Wk
constexpr int SEG2 = SEG1 + 512;     // tconv Wv
constexpr int SEG3 = SEG2 + 256;     // tconv Win(top rows offset 512)
constexpr int SEG4 = SEG3 + 16000;   // tconv Wd
constexpr int SEG5 = SEG4 + 2048;    // gather
constexpr int SEG6 = SEG5 + 128;     // copy h
constexpr int PREP_BLOCKS = SEG6;

__global__ __launch_bounds__(256) void prep_all_kernel(
    const float* __restrict__ enc, const float* __restrict__ Wk,
    const float* __restrict__ Wv, const float* __restrict__ Win,
    const float* __restrict__ Wd, const int* __restrict__ x,
    const float* __restrict__ emb, const float* __restrict__ h0)
{
    __shared__ float t[32 * 33];
    int blk = blockIdx.x, tid = threadIdx.x;
    if (blk < SEG0) {
        int i = blk * 256 + tid;
        float4 v = ((const float4*)enc)[i];
        __nv_bfloat16 h0_, h1_, h2_, h3_, l0_, l1_, l2_, l3_;
        bsplit(v.x, h0_, l0_); bsplit(v.y, h1_, l1_);
        bsplit(v.z, h2_, l2_); bsplit(v.w, h3_, l3_);
        ((__nv_bfloat162*)g_enc_h)[2 * i]     = __nv_bfloat162(h0_, h1_);
        ((__nv_bfloat162*)g_enc_h)[2 * i + 1] = __nv_bfloat162(h2_, h3_);
        ((__nv_bfloat162*)g_enc_l)[2 * i]     = __nv_bfloat162(l0_, l1_);
        ((__nv_bfloat162*)g_enc_l)[2 * i + 1] = __nv_bfloat162(l2_, l3_);
    } else if (blk < SEG1) {
        int i = blk - SEG0;
        tconv_body(Wk, 2 * H_, H_, 0, g_Wkt_h, g_Wkt_l, i % 16, i / 16, t);
    } else if (blk < SEG2) {
        int i = blk - SEG1;
        tconv_body(Wv, 2 * H_, H_, 0, g_Wvt_h, g_Wvt_l, i % 16, i / 16, t);
    } else if (blk < SEG3) {
        int i = blk - SEG2;
        tconv_body(Win, H_, H_, 512, g_Wint_h, g_Wint_l, i % 16, i / 16, t);
    } else if (blk < SEG4) {
        int i = blk - SEG3;
        tconv_body(Wd, H_, V_, 0, g_Wdt_h, g_Wdt_l, i % 1000, i / 1000, t);
    } else if (blk < SEG5) {
        int r = blk - SEG4;
        int tt = r >> 5, b = r & 31;
        int tok = x[b * TD + tt];
        const float* src = emb + (size_t)tok * E_;
        for (int i = tid; i < E_; i += 256) {
            __nv_bfloat16 h, l; bsplit(src[i], h, l);
            g_eseq_h[(size_t)r * E_ + i] = h;
            g_eseq_l[(size_t)r * E_ + i] = l;
        }
    } else {
        int i = (blk - SEG5) * 256 + tid;
        g_hA[i] = h0[i];
    }
}

// ---------------- fp32 SIMT GEMM (Wcomb^T only) ------------------------------
__global__ __launch_bounds__(256) void sgemm_kernel(
    int M, int N, int K,
    const float* __restrict__ A, int lda,
    const float* __restrict__ B, int ldb,
    float* __restrict__ C, int mode)
{
    __shared__ float As[8][132];
    __shared__ float Bs[8][132];
    const int tid = threadIdx.x;
    const int bx = blockIdx.x, by = blockIdx.y;
    const float* Aptr = A + (size_t)(by * 128 + (tid >> 1)) * lda + (tid & 1) * 4;
    const float* Bptr = B + (size_t)(tid >> 5) * ldb + bx * 128 + (tid & 31) * 4;
    const int ty = tid >> 4, tx = tid & 15;
    float acc[8][8];
#pragma unroll
    for (int i = 0; i < 8; i++)
#pragma unroll
        for (int j = 0; j < 8; j++) acc[i][j] = 0.f;
    for (int k0 = 0; k0 < K; k0 += 8) {
        float4 av = *(const float4*)(Aptr + k0);
        float4 bv = *(const float4*)(Bptr + (size_t)k0 * ldb);
        __syncthreads();
        const int ar_ = tid >> 1, ac_ = (tid & 1) * 4;
        As[ac_ + 0][ar_] = av.x; As[ac_ + 1][ar_] = av.y;
        As[ac_ + 2][ar_] = av.z; As[ac_ + 3][ar_] = av.w;
        *(float4*)&Bs[tid >> 5][(tid & 31) * 4] = bv;
        __syncthreads();
#pragma unroll
        for (int kk = 0; kk < 8; kk++) {
            float ar[8], br[8];
            *(float4*)(ar)     = *(float4*)&As[kk][ty * 4];
            *(float4*)(ar + 4) = *(float4*)&As[kk][ty * 4 + 64];
            *(float4*)(br)     = *(float4*)&Bs[kk][tx * 4];
            *(float4*)(br + 4) = *(float4*)&Bs[kk][tx * 4 + 64];
#pragma unroll
            for (int i = 0; i < 8; i++)
#pragma unroll
                for (int j = 0; j < 8; j++) acc[i][j] += ar[i] * br[j];
        }
    }
#pragma unroll
    for (int i = 0; i < 8; i++) {
        int m = by * 128 + ty * 4 + (i & 3) + (i >> 2) * 64;
#pragma unroll
        for (int j = 0; j < 8; j++) {
            int n = bx * 128 + tx * 4 + (j & 3) + (j >> 2) * 64;
            if (mode == 0) C[(size_t)m * N + n] = acc[i][j];
            else           C[(size_t)n * M + m] = acc[i][j];   // transposed write
        }
    }
}

// ---------------- transpose Kh (b,s,h,d) -> Kh2 (b,h,d,s) --------------------
__global__ void transpose_k_kernel()
{
    __shared__ float t[32][33];
    int bh = blockIdx.x;
    int b = bh >> 3, h = bh & 7;
    int s0 = blockIdx.y * 32, d0 = blockIdx.z * 32;
    for (int yy = threadIdx.y; yy < 32; yy += 8)
        t[yy][threadIdx.x] = g_Kh[((size_t)(b * 256 + s0 + yy) * 8 + h) * 64 + d0 + threadIdx.x];
    __syncthreads();
    for (int yy = threadIdx.y; yy < 32; yy += 8)
        g_Kh2[((size_t)(bh) * 64 + d0 + yy) * 256 + s0 + threadIdx.x] = t[threadIdx.x][yy];
}

__global__ void copy_kernel(const float* __restrict__ src, float* __restrict__ dst, int n)
{
    int i = blockIdx.x * blockDim.x + threadIdx.x;
    if (i < n) dst[i] = src[i];
}

__global__ void reset_kernel() { g_bar = 0; }

// =================== PERSISTENT SCAN KERNEL ==================================
constexpr int OFF_W   = 0;        // 24576
constexpr int OFF_BF  = 24576;    // 16640
constexpr int OFF_GP  = 41216;    // 3072
constexpr int OFF_AT  = 44288;    // 2176
constexpr int OFF_MU  = 46464;    // 32
constexpr int OFF_RS  = 46496;    // 32
constexpr int OFF_HPV = 46528;    // 128
constexpr int SCAN_SMEM_FLOATS = 46656;
constexpr int BFS = 520;

__device__ __forceinline__ void grid_bar(int& epoch) {
    __syncthreads();
    epoch += NBLK;
    if (threadIdx.x == 0) {
        int* p = &g_bar;
        asm volatile("red.release.gpu.global.add.s32 [%0], 1;" :: "l"(p) : "memory");
        int v;
        do {
            asm volatile("ld.acquire.gpu.global.s32 %0, [%1];" : "=r"(v) : "l"(p) : "memory");
        } while (v < epoch);
    }
    __syncthreads();
}

__global__ __launch_bounds__(NTHR, 1) void scan_kernel(
    const float* __restrict__ Wq,  const int* __restrict__ vlen,
    const float* __restrict__ Wih, const float* __restrict__ Whh,
    const float* __restrict__ bih, const float* __restrict__ bhh,
    const float* __restrict__ lng, const float* __restrict__ lnb,
    const float* __restrict__ alph)
{
    extern __shared__ float sm[];
    float* w   = sm + OFF_W;
    float* bf  = sm + OFF_BF;
    float* gp  = sm + OFF_GP;
    float* at  = sm + OFF_AT;
    float* mu  = sm + OFF_MU;
    float* rs  = sm + OFF_RS;
    float* hpv = sm + OFF_HPV;

    const int tid = threadIdx.x, lane = tid & 31, wid = tid >> 5;
    const int blk = blockIdx.x;
    int epoch = 0;

    for (int i = tid; i < 24576; i += NTHR) {
        int unit = i >> 9, k = i & 511;
        int l = unit / 24, rem = unit % 24;
        int jl = rem / 6, g = rem % 6;
        int jg = blk * 4 + jl;
        const float* src = (g < 3)
            ? (Wih + ((size_t)l * 3 * 512 + g * 512 + jg) * 512)
            : (Whh + ((size_t)l * 3 * 512 + (g - 3) * 512 + jg) * 512);
        w[i] = src[k];
    }
    __syncthreads();

    for (int t = 0; t < TD; t++) {
        const float* hin  = (t & 1) ? g_hB : g_hA;
        float*       hout = (t & 1) ? g_hA : g_hB;

        // ================= phase 1: attention ================================
        {
            int grp = tid >> 8, lt = tid & 255;
            int u = blk * 2 + grp;
            int b = u >> 3, h = u & 7;
            float* sh_ = at + grp * 1088;
            float* sq_ = sh_ + 512;
            float* sp_ = sq_ + 64;
            float* rd_ = sp_ + 256;
            const float* hlast = hin + (L_ - 1) * B_ * H_ + b * 512;

            sh_[lt] = hlast[lt];
            sh_[lt + 256] = hlast[lt + 256];
            __syncthreads();

            int d = lt & 63, c = lt >> 6;
            {
                float acc = 0.f;
                const float* wq = Wq + h * 64 + d;
#pragma unroll 8
                for (int k = c * 128; k < c * 128 + 128; k++)
                    acc += sh_[k] * wq[(size_t)k * 512];
                rd_[lt] = acc;
            }
            __syncthreads();
            if (lt < 64) sq_[lt] = rd_[lt] + rd_[lt + 64] + rd_[lt + 128] + rd_[lt + 192];
            __syncthreads();

            float sc = -1e6f;
            int vl = vlen[b];
            if (lt < vl) {
                float a = 0.f;
                const float* kp = g_Kh2 + (size_t)u * 64 * 256 + lt;
#pragma unroll 8
                for (int dd = 0; dd < 64; dd++) a += sq_[dd] * kp[dd * 256];
                sc = a * 0.125f;
            }
            int wg = lt >> 5;
            float m = sc;
#pragma unroll
            for (int o = 16; o; o >>= 1) m = fmaxf(m, __shfl_xor_sync(0xffffffffu, m, o));
            if ((lt & 31) == 0) rd_[wg] = m;
            __syncthreads();
            float mx = rd_[0];
#pragma unroll
            for (int i = 1; i < 8; i++) mx = fmaxf(mx, rd_[i]);
            float p = __expf(sc - mx);
            float s = p;
#pragma unroll
            for (int o = 16; o; o >>= 1) s += __shfl_xor_sync(0xffffffffu, s, o);
            if ((lt & 31) == 0) rd_[8 + wg] = s;
            __syncthreads();
            float sum = rd_[8];
#pragma unroll
            for (int i = 1; i < 8; i++) sum += rd_[8 + i];
            sp_[lt] = p / sum;
            __syncthreads();

            {
                float a = 0.f;
                const float* vp = g_Vh + ((size_t)(b * 256 + c * 64) * 8 + h) * 64 + d;
#pragma unroll 8
                for (int ss = 0; ss < 64; ss++) a += sp_[c * 64 + ss] * vp[(size_t)ss * 512];
                rd_[lt] = a;
            }
            __syncthreads();
            if (lt < 64)
                g_ctx[b * 512 + h * 64 + lt] =
                    rd_[lt] + rd_[lt + 64] + rd_[lt + 128] + rd_[lt + 192];
        }
        grid_bar(epoch);

        // ================= phase 2: xr = ctx @ Wcomb + eproj[t] =============
        for (int i = tid; i < 16384; i += NTHR) {
            int b = i >> 9, k = i & 511;
            bf[b * BFS + k] = g_ctx[i];
        }
        __syncthreads();
        {
            int jl = wid >> 2, kq = wid & 3;
            int jg = blk * 4 + jl;
            const float* wc = g_Wcombt + (size_t)jg * 512 + kq * 128;
            const float* xrow = bf + lane * BFS + kq * 128;
            float acc = 0.f;
#pragma unroll
            for (int k0 = 0; k0 < 128; k0 += 4) {
                float4 wv = *(const float4*)(wc + k0);
                float4 xv = *(const float4*)(xrow + k0);
                acc += wv.x * xv.x + wv.y * xv.y + wv.z * xv.z + wv.w * xv.w;
            }
            gp[(jl * 4 + kq) * 32 + lane] = acc;
        }
        __syncthreads();
        if (tid < 128) {
            int jl = tid >> 5, b = tid & 31, jg = blk * 4 + jl;
            float v = gp[(jl * 4 + 0) * 32 + b] + gp[(jl * 4 + 1) * 32 + b]
                    + gp[(jl * 4 + 2) * 32 + b] + gp[(jl * 4 + 3) * 32 + b];
            g_xra[b * 512 + jg] = v + g_eproj[(size_t)(t * B_ + b) * H_ + jg];
        }
        grid_bar(epoch);

        // ================= phases 3,4: GRU layers ===========================
        for (int l = 0; l < 2; l++) {
            const float* xr = (l == 0) ? g_xra : g_xrb;
            const float* hsrc = hin + l * B_ * H_;
            float* hdst = hout + l * B_ * H_;

            for (int i = tid; i < 16384; i += NTHR) {
                int b = i >> 9, k = i & 511;
                bf[b * BFS + k] = hsrc[i];
            }
            __syncthreads();
            if (tid < 128) {
                int jl = tid >> 5, b = tid & 31;
                hpv[tid] = bf[b * BFS + blk * 4 + jl];
            }
            // hh sub-phase
            {
                int jl = wid >> 2, kq = wid & 3;
                const float* wb = w + (((l * 4 + jl) * 6) + 3) * 512 + kq * 128;
                const float* xrow = bf + lane * BFS + kq * 128;
                float a0 = 0.f, a1 = 0.f, a2 = 0.f;
#pragma unroll
                for (int k0 = 0; k0 < 128; k0 += 4) {
                    float4 xv = *(const float4*)(xrow + k0);
                    float4 w0 = *(const float4*)(wb + k0);
                    float4 w1 = *(const float4*)(wb + 512 + k0);
                    float4 w2 = *(const float4*)(wb + 1024 + k0);
                    a0 += w0.x * xv.x + w0.y * xv.y + w0.z * xv.z + w0.w * xv.w;
                    a1 += w1.x * xv.x + w1.y * xv.y + w1.z * xv.z + w1.w * xv.w;
                    a2 += w2.x * xv.x + w2.y * xv.y + w2.z * xv.z + w2.w * xv.w;
                }
                gp[((jl * 3 + 0) * 4 + kq) * 32 + lane] = a0;
                gp[((jl * 3 + 1) * 4 + kq) * 32 + lane] = a1;
                gp[((jl * 3 + 2) * 4 + kq) * 32 + lane] = a2;
            }
            __syncthreads();
            // LN stats (2 rows per warp)
            {
#pragma unroll
                for (int rr = 0; rr < 2; rr++) {
                    int b = wid * 2 + rr;
                    float s1 = 0.f, s2 = 0.f;
#pragma unroll
                    for (int kk = 0; kk < 16; kk++) {
                        float v = xr[b * 512 + lane + kk * 32];
                        s1 += v; s2 += v * v;
                    }
#pragma unroll
                    for (int o = 16; o; o >>= 1) {
                        s1 += __shfl_xor_sync(0xffffffffu, s1, o);
                        s2 += __shfl_xor_sync(0xffffffffu, s2, o);
                    }
                    if (lane == 0) {
                        float m = s1 * (1.f / 512.f);
                        float var = s2 * (1.f / 512.f) - m * m;
                        mu[b] = m;
                        rs[b] = rsqrtf(var + 1e-5f);
                    }
                }
            }
            __syncthreads();
            for (int i = tid; i < 16384; i += NTHR) {
                int b = i >> 9, k = i & 511;
                bf[b * BFS + k] = (xr[i] - mu[b]) * rs[b] * lng[l * 512 + k] + lnb[l * 512 + k];
            }
            __syncthreads();
            // ih sub-phase
            {
                int jl = wid >> 2, kq = wid & 3;
                const float* wb = w + ((l * 4 + jl) * 6) * 512 + kq * 128;
                const float* xrow = bf + lane * BFS + kq * 128;
                float a0 = 0.f, a1 = 0.f, a2 = 0.f;
#pragma unroll
                for (int k0 = 0; k0 < 128; k0 += 4) {
                    float4 xv = *(const float4*)(xrow + k0);
                    float4 w0 = *(const float4*)(wb + k0);
                    float4 w1 = *(const float4*)(wb + 512 + k0);
                    float4 w2 = *(const float4*)(wb + 1024 + k0);
                    a0 += w0.x * xv.x + w0.y * xv.y + w0.z * xv.z + w0.w * xv.w;
                    a1 += w1.x * xv.x + w1.y * xv.y + w1.z * xv.z + w1.w * xv.w;
                    a2 += w2.x * xv.x + w2.y * xv.y + w2.z * xv.z + w2.w * xv.w;
                }
                gp[1536 + ((jl * 3 + 0) * 4 + kq) * 32 + lane] = a0;
                gp[1536 + ((jl * 3 + 1) * 4 + kq) * 32 + lane] = a1;
                gp[1536 + ((jl * 3 + 2) * 4 + kq) * 32 + lane] = a2;
            }
            __syncthreads();
            if (tid < 128) {
                int jl = tid >> 5, b = tid & 31, jg = blk * 4 + jl;
                float hr = 0.f, hz = 0.f, hg = 0.f, ir = 0.f, iz = 0.f, ig = 0.f;
#pragma unroll
                for (int kq = 0; kq < 4; kq++) {
                    hr += gp[((jl * 3 + 0) * 4 + kq) * 32 + b];
                    hz += gp[((jl * 3 + 1) * 4 + kq) * 32 + b];
                    hg += gp[((jl * 3 + 2) * 4 + kq) * 32 + b];
                    ir += gp[1536 + ((jl * 3 + 0) * 4 + kq) * 32 + b];
                    iz += gp[1536 + ((jl * 3 + 1) * 4 + kq) * 32 + b];
                    ig += gp[1536 + ((jl * 3 + 2) * 4 + kq) * 32 + b];
                }
                ir += bih[l * 1536 + jg];        hr += bhh[l * 1536 + jg];
                iz += bih[l * 1536 + 512 + jg];  hz += bhh[l * 1536 + 512 + jg];
                ig += bih[l * 1536 + 1024 + jg]; hg += bhh[l * 1536 + 1024 + jg];
                float r = fsig(ir + hr);
                float z = fsig(iz + hz);
                float g = ftanh(ig + r * hg);
                float hn = (1.f - z) * g + z * hpv[tid];
                hdst[b * 512 + jg] = hn;
                float yv = xr[b * 512 + jg] + alph[l] * hn;
                if (l == 0) {
                    g_xrb[b * 512 + jg] = yv;
                } else {
                    __nv_bfloat16 yh, yl; bsplit(yv, yh, yl);
                    size_t o = (size_t)(t * B_ + b) * 512 + jg;
                    g_ys_h[o] = yh;
                    g_ys_l[o] = yl;
                }
            }
            grid_bar(epoch);
        }
    }
}

// ============================ host orchestration ============================
extern "C" void kernel_launch(void* const* d_in, const int* in_sizes, int n_in,
                              void* d_out, int out_size)
{
    const int*   x    = (const int*)  d_in[0];
    const float* enc  = (const float*)d_in[1];
    const float* h0   = (const float*)d_in[2];
    const int*   vlen = (const int*)  d_in[3];
    const float* emb  = (const float*)d_in[4];
    const float* Wq   = (const float*)d_in[5];
    const float* Wk   = (const float*)d_in[6];
    const float* Wv   = (const float*)d_in[7];
    const float* Wo   = (const float*)d_in[8];
    const float* Win  = (const float*)d_in[9];
    const float* lng  = (const float*)d_in[10];
    const float* lnb  = (const float*)d_in[11];
    const float* alph = (const float*)d_in[12];
    const float* Wih  = (const float*)d_in[13];
    const float* Whh  = (const float*)d_in[14];
    const float* bih  = (const float*)d_in[15];
    const float* bhh  = (const float*)d_in[16];
    const float* Wd   = (const float*)d_in[17];
    const float* bd   = (const float*)d_in[18];
    float* out = (float*)d_out;

    cudaFuncSetAttribute(scan_kernel, cudaFuncAttributeMaxDynamicSharedMemorySize,
                         SCAN_SMEM_FLOATS * 4);

    float *pKh, *pVh, *pEproj, *pWcombT, *pHA;
    __nv_bfloat16 *pEncH, *pEncL, *pWktH, *pWktL, *pWvtH, *pWvtL, *pWintH, *pWintL;
    __nv_bfloat16 *pWdtH, *pWdtL, *pEsH, *pEsL, *pYsH, *pYsL;
    cudaGetSymbolAddress((void**)&pKh,     g_Kh);
    cudaGetSymbolAddress((void**)&pVh,     g_Vh);
    cudaGetSymbolAddress((void**)&pEproj,  g_eproj);
    cudaGetSymbolAddress((void**)&pWcombT, g_Wcombt);
    cudaGetSymbolAddress((void**)&pHA,     g_hA);
    cudaGetSymbolAddress((void**)&pEncH,   g_enc_h);
    cudaGetSymbolAddress((void**)&pEncL,   g_enc_l);
    cudaGetSymbolAddress((void**)&pWktH,   g_Wkt_h);
    cudaGetSymbolAddress((void**)&pWktL,   g_Wkt_l);
    cudaGetSymbolAddress((void**)&pWvtH,   g_Wvt_h);
    cudaGetSymbolAddress((void**)&pWvtL,   g_Wvt_l);
    cudaGetSymbolAddress((void**)&pWintH,  g_Wint_h);
    cudaGetSymbolAddress((void**)&pWintL,  g_Wint_l);
    cudaGetSymbolAddress((void**)&pWdtH,   g_Wdt_h);
    cudaGetSymbolAddress((void**)&pWdtL,   g_Wdt_l);
    cudaGetSymbolAddress((void**)&pEsH,    g_eseq_h);
    cudaGetSymbolAddress((void**)&pEsL,    g_eseq_l);
    cudaGetSymbolAddress((void**)&pYsH,    g_ys_h);
    cudaGetSymbolAddress((void**)&pYsL,    g_ys_l);

    // launch 0: fused prep (conversions + gather + h copy)
    prep_all_kernel<<<PREP_BLOCKS, 256>>>(enc, Wk, Wv, Win, Wd, x, emb, h0);

    // launch 1: batched K/V/eproj HMMA projections
    mma_batched_kernel<<<dim3(4, 64, 3), 256>>>(
        pEncH, pEncL, pWktH, pWktL, pWvtH, pWvtL,
        pEsH, pEsL, pWintH, pWintL, pKh, pVh, pEproj);

    // launch 2: W_comb^T = (W_o @ W_in[:512])^T (transposed write)
    sgemm_kernel<<<dim3(4, 4), 256>>>(H_, H_, H_, Wo, H_, Win, H_, pWcombT, 1);

    // launch 3: Kh transpose
    transpose_k_kernel<<<dim3(B_ * NH, TE / 32, DH / 32), dim3(32, 8)>>>();

    // launch 4: barrier reset
    reset_kernel<<<1, 1>>>();

    // launch 5 (ncu -s 5 profiles this): the whole 64-step scan
    scan_kernel<<<NBLK, NTHR, SCAN_SMEM_FLOATS * 4>>>(
        Wq, vlen, Wih, Whh, bih, bhh, lng, lnb, alph);

    // launch 6: logits (HMMA, pipelined), transposed write to (B,T,V)
    mma_gemm_kernel<<<dim3(V_ / 128, (TD * B_) / 128), 256>>>(
        TD * B_, V_, H_, pYsH, pYsL, pWdtH, pWdtL, out, bd, 1);

    // launch 7: final hidden state (t=63 odd -> final state lives in g_hA)
    if (out_size >= BTV + LBH)
        copy_kernel<<<(LBH + 255) / 256, 256>>>(pHA, out + BTV, LBH);
}

// round 8
// speedup vs baseline: 1.0925x; 1.0925x over previous
#include <cuda_runtime.h>
#include <cuda_bf16.h>
#include <math.h>
#include <stdint.h>

constexpr int B_  = 32;
constexpr int TD  = 64;
constexpr int TE  = 256;
constexpr int H_  = 512;
constexpr int E_  = 512;
constexpr int V_  = 32000;
constexpr int L_  = 2;
constexpr int NH  = 8;
constexpr int DH  = 64;
constexpr int BTV = B_ * TD * V_;
constexpr int LBH = L_ * B_ * H_;

constexpr int NBLK = 128;
constexpr int NTHR = 512;

// ---------------- scratch (device globals) ----------------------------------
__device__ __align__(16) float g_Kh  [B_ * TE * H_];
__device__ __align__(16) float g_Kh2 [B_ * NH * DH * TE];
__device__ __align__(16) float g_Vh  [B_ * TE * H_];
__device__ __align__(16) float g_eproj[TD * B_ * H_];
__device__ __align__(16) float g_Wcombt[H_ * H_];
__device__ __align__(16) float g_hA[LBH];
__device__ __align__(16) float g_hB[LBH];
__device__ __align__(16) float g_ctx[B_ * H_];
__device__ __align__(16) float g_xra[B_ * H_];
__device__ __align__(16) float g_xrb[B_ * H_];
__device__ int g_bar;

__device__ __align__(16) __nv_bfloat16 g_enc_h [B_ * TE * 2 * H_];
__device__ __align__(16) __nv_bfloat16 g_enc_l [B_ * TE * 2 * H_];
__device__ __align__(16) __nv_bfloat16 g_Wkt_h [H_ * 2 * H_];
__device__ __align__(16) __nv_bfloat16 g_Wkt_l [H_ * 2 * H_];
__device__ __align__(16) __nv_bfloat16 g_Wvt_h [H_ * 2 * H_];
__device__ __align__(16) __nv_bfloat16 g_Wvt_l [H_ * 2 * H_];
__device__ __align__(16) __nv_bfloat16 g_Wint_h[H_ * H_];
__device__ __align__(16) __nv_bfloat16 g_Wint_l[H_ * H_];
__device__ __align__(16) __nv_bfloat16 g_Wdt_h [V_ * H_];
__device__ __align__(16) __nv_bfloat16 g_Wdt_l [V_ * H_];
__device__ __align__(16) __nv_bfloat16 g_eseq_h[TD * B_ * E_];
__device__ __align__(16) __nv_bfloat16 g_eseq_l[TD * B_ * E_];
__device__ __align__(16) __nv_bfloat16 g_ys_h  [TD * B_ * H_];
__device__ __align__(16) __nv_bfloat16 g_ys_l  [TD * B_ * H_];

// ======================= helpers =============================================
__device__ __forceinline__ uint32_t smem_u32(const void* p) {
    uint32_t a;
    asm("{ .reg .u64 t; cvta.to.shared.u64 t, %1; cvt.u32.u64 %0, t; }"
        : "=r"(a) : "l"(p));
    return a;
}
__device__ __forceinline__ void ldsm4(uint32_t (&r)[4], uint32_t addr) {
    asm volatile("ldmatrix.sync.aligned.m8n8.x4.shared.b16 {%0,%1,%2,%3}, [%4];"
        : "=r"(r[0]), "=r"(r[1]), "=r"(r[2]), "=r"(r[3]) : "r"(addr));
}
__device__ __forceinline__ void mma16816(float (&d)[4], const uint32_t (&a)[4],
                                         uint32_t b0, uint32_t b1) {
    asm volatile(
        "mma.sync.aligned.m16n8k16.row.col.f32.bf16.bf16.f32 "
        "{%0,%1,%2,%3}, {%4,%5,%6,%7}, {%8,%9}, {%0,%1,%2,%3};"
        : "+f"(d[0]), "+f"(d[1]), "+f"(d[2]), "+f"(d[3])
        : "r"(a[0]), "r"(a[1]), "r"(a[2]), "r"(a[3]), "r"(b0), "r"(b1));
}
__device__ __forceinline__ float fsig(float x) {
    return 1.f / (1.f + __expf(-x));
}
__device__ __forceinline__ float ftanh(float x) {
    return 2.f / (1.f + __expf(-2.f * x)) - 1.f;
}
__device__ __forceinline__ void bsplit(float x, __nv_bfloat16& h, __nv_bfloat16& l) {
    h = __float2bfloat16(x);
    l = __float2bfloat16(x - __bfloat162float(h));
}

// ============ HMMA compensated-bf16 GEMM body (pipelined) ====================
constexpr int BKg  = 32;
constexpr int LDSg = BKg + 8;

__device__ __forceinline__ void mma_gemm_body(
    __nv_bfloat16* sAh, __nv_bfloat16* sAl, __nv_bfloat16* sBh, __nv_bfloat16* sBl,
    int M, int N, int K,
    const __nv_bfloat16* __restrict__ Ah, const __nv_bfloat16* __restrict__ Al,
    const __nv_bfloat16* __restrict__ Bh, const __nv_bfloat16* __restrict__ Bl,
    float* __restrict__ C, const float* __restrict__ bias, int mode,
    int bx, int by)
{
    const int tid = threadIdx.x, lane = tid & 31, wid = tid >> 5;
    const int wm = wid >> 1, wn = wid & 1;
    const int n0 = bx * 128, m0 = by * 128;

    float acc[2][8][4];
#pragma unroll
    for (int i = 0; i < 2; i++)
#pragma unroll
        for (int j = 0; j < 8; j++)
#pragma unroll
            for (int k = 0; k < 4; k++) acc[i][j][k] = 0.f;

    const int lrow = tid >> 2;
    const int lcol = (tid & 3) * 8;

    uint4 rAh[2], rAl[2], rBh[2], rBl[2];
#pragma unroll
    for (int h = 0; h < 2; h++) {
        int row = lrow + h * 64;
        size_t ga = (size_t)(m0 + row) * K + lcol;
        size_t gb = (size_t)(n0 + row) * K + lcol;
        rAh[h] = *(const uint4*)(Ah + ga);
        rAl[h] = *(const uint4*)(Al + ga);
        rBh[h] = *(const uint4*)(Bh + gb);
        rBl[h] = *(const uint4*)(Bl + gb);
    }

    const int nchunks = K >> 5;
    for (int kc = 0; kc < nchunks; kc++) {
        __syncthreads();
#pragma unroll
        for (int h = 0; h < 2; h++) {
            int row = lrow + h * 64;
            uint32_t so = row * LDSg + lcol;
            *(uint4*)&sAh[so] = rAh[h];
            *(uint4*)&sAl[so] = rAl[h];
            *(uint4*)&sBh[so] = rBh[h];
            *(uint4*)&sBl[so] = rBl[h];
        }
        __syncthreads();
        if (kc + 1 < nchunks) {
            int kb = (kc + 1) << 5;
#pragma unroll
            for (int h = 0; h < 2; h++) {
                int row = lrow + h * 64;
                size_t ga = (size_t)(m0 + row) * K + kb + lcol;
                size_t gb = (size_t)(n0 + row) * K + kb + lcol;
                rAh[h] = *(const uint4*)(Ah + ga);
                rAl[h] = *(const uint4*)(Al + ga);
                rBh[h] = *(const uint4*)(Bh + gb);
                rBl[h] = *(const uint4*)(Bl + gb);
            }
        }

#pragma unroll
        for (int ks = 0; ks < BKg; ks += 16) {
            uint32_t ah[2][4], al[2][4];
            const uint32_t fcol = ks + (lane >> 4) * 8;
#pragma unroll
            for (int mi = 0; mi < 2; mi++) {
                uint32_t arow = wm * 32 + mi * 16 + (lane & 15);
                ldsm4(ah[mi], smem_u32(&sAh[arow * LDSg + fcol]));
                ldsm4(al[mi], smem_u32(&sAl[arow * LDSg + fcol]));
            }
#pragma unroll
            for (int nj = 0; nj < 4; nj++) {
                uint32_t brow = wn * 64 + nj * 16 + (lane & 15);
                uint32_t bh[4], bl[4];
                ldsm4(bh, smem_u32(&sBh[brow * LDSg + fcol]));
                ldsm4(bl, smem_u32(&sBl[brow * LDSg + fcol]));
#pragma unroll
                for (int mi = 0; mi < 2; mi++) {
                    mma16816(acc[mi][2 * nj],     ah[mi], bh[0], bh[2]);
                    mma16816(acc[mi][2 * nj + 1], ah[mi], bh[1], bh[3]);
                    mma16816(acc[mi][2 * nj],     ah[mi], bl[0], bl[2]);
                    mma16816(acc[mi][2 * nj + 1], ah[mi], bl[1], bl[3]);
                    mma16816(acc[mi][2 * nj],     al[mi], bh[0], bh[2]);
                    mma16816(acc[mi][2 * nj + 1], al[mi], bh[1], bh[3]);
                }
            }
        }
    }

#pragma unroll
    for (int mi = 0; mi < 2; mi++) {
        int row = m0 + wm * 32 + mi * 16 + (lane >> 2);
#pragma unroll
        for (int nt = 0; nt < 8; nt++) {
            int col = n0 + wn * 64 + nt * 8 + (lane & 3) * 2;
            float bb0 = bias ? bias[col] : 0.f;
            float bb1 = bias ? bias[col + 1] : 0.f;
            float2 v0 = make_float2(acc[mi][nt][0] + bb0, acc[mi][nt][1] + bb1);
            float2 v1 = make_float2(acc[mi][nt][2] + bb0, acc[mi][nt][3] + bb1);
            if (mode == 0) {
                *(float2*)&C[(size_t)row * N + col] = v0;
                *(float2*)&C[(size_t)(row + 8) * N + col] = v1;
            } else {
                int t0 = row >> 5, b0v_ = row & 31;
                int t1 = (row + 8) >> 5, b1v_ = (row + 8) & 31;
                *(float2*)&C[(size_t)b0v_ * (TD * V_) + (size_t)t0 * V_ + col] = v0;
                *(float2*)&C[(size_t)b1v_ * (TD * V_) + (size_t)t1 * V_ + col] = v1;
            }
        }
    }
}

__global__ __launch_bounds__(256, 2) void mma_gemm_kernel(
    int M, int N, int K,
    const __nv_bfloat16* __restrict__ Ah, const __nv_bfloat16* __restrict__ Al,
    const __nv_bfloat16* __restrict__ Bh, const __nv_bfloat16* __restrict__ Bl,
    float* __restrict__ C, const float* __restrict__ bias, int mode)
{
    __shared__ __nv_bfloat16 sAh[128 * LDSg], sAl[128 * LDSg];
    __shared__ __nv_bfloat16 sBh[128 * LDSg], sBl[128 * LDSg];
    mma_gemm_body(sAh, sAl, sBh, sBl, M, N, K, Ah, Al, Bh, Bl, C, bias, mode,
                  blockIdx.x, blockIdx.y);
}

// fp32 SIMT GEMM body (512x512x512, transposed write) for Wcomb^T
__device__ void sgemm_tr_body(float* As, float* Bs,   // [8*132] each
    const float* __restrict__ A, const float* __restrict__ B,
    float* __restrict__ C, int bx, int by)
{
    const int tid = threadIdx.x;
    const float* Aptr = A + (size_t)(by * 128 + (tid >> 1)) * 512 + (tid & 1) * 4;
    const float* Bptr = B + (size_t)(tid >> 5) * 512 + bx * 128 + (tid & 31) * 4;
    const int ty = tid >> 4, tx = tid & 15;
    float acc[8][8];
#pragma unroll
    for (int i = 0; i < 8; i++)
#pragma unroll
        for (int j = 0; j < 8; j++) acc[i][j] = 0.f;
    for (int k0 = 0; k0 < 512; k0 += 8) {
        float4 av = *(const float4*)(Aptr + k0);
        float4 bv = *(const float4*)(Bptr + (size_t)k0 * 512);
        __syncthreads();
        const int ar_ = tid >> 1, ac_ = (tid & 1) * 4;
        As[(ac_ + 0) * 132 + ar_] = av.x; As[(ac_ + 1) * 132 + ar_] = av.y;
        As[(ac_ + 2) * 132 + ar_] = av.z; As[(ac_ + 3) * 132 + ar_] = av.w;
        *(float4*)&Bs[(tid >> 5) * 132 + (tid & 31) * 4] = bv;
        __syncthreads();
#pragma unroll
        for (int kk = 0; kk < 8; kk++) {
            float ar[8], br[8];
            *(float4*)(ar)     = *(float4*)&As[kk * 132 + ty * 4];
            *(float4*)(ar + 4) = *(float4*)&As[kk * 132 + ty * 4 + 64];
            *(float4*)(br)     = *(float4*)&Bs[kk * 132 + tx * 4];
            *(float4*)(br + 4) = *(float4*)&Bs[kk * 132 + tx * 4 + 64];
#pragma unroll
            for (int i = 0; i < 8; i++)
#pragma unroll
                for (int j = 0; j < 8; j++) acc[i][j] += ar[i] * br[j];
        }
    }
#pragma unroll
    for (int i = 0; i < 8; i++) {
        int m = by * 128 + ty * 4 + (i & 3) + (i >> 2) * 64;
#pragma unroll
        for (int j = 0; j < 8; j++) {
            int n = bx * 128 + tx * 4 + (j & 3) + (j >> 2) * 64;
            C[(size_t)n * 512 + m] = acc[i][j];   // transposed: C[n][m]
        }
    }
}

// batched K/V/eproj HMMA projections + Wcomb^T sgemm in one launch (z selects)
__global__ __launch_bounds__(256, 2) void mma_batched_kernel(
    const __nv_bfloat16* __restrict__ encH, const __nv_bfloat16* __restrict__ encL,
    const __nv_bfloat16* __restrict__ WkH,  const __nv_bfloat16* __restrict__ WkL,
    const __nv_bfloat16* __restrict__ WvH,  const __nv_bfloat16* __restrict__ WvL,
    const __nv_bfloat16* __restrict__ esH,  const __nv_bfloat16* __restrict__ esL,
    const __nv_bfloat16* __restrict__ WinH, const __nv_bfloat16* __restrict__ WinL,
    float* __restrict__ Kh, float* __restrict__ Vh, float* __restrict__ eproj,
    const float* __restrict__ Wo, const float* __restrict__ Win,
    float* __restrict__ WcombT)
{
    __shared__ __nv_bfloat16 sAh[128 * LDSg], sAl[128 * LDSg];
    __shared__ __nv_bfloat16 sBh[128 * LDSg], sBl[128 * LDSg];
    int z = blockIdx.z;
    if (z == 0) {
        mma_gemm_body(sAh, sAl, sBh, sBl, B_ * TE, H_, 2 * H_,
                      encH, encL, WkH, WkL, Kh, nullptr, 0, blockIdx.x, blockIdx.y);
    } else if (z == 1) {
        mma_gemm_body(sAh, sAl, sBh, sBl, B_ * TE, H_, 2 * H_,
                      encH, encL, WvH, WvL, Vh, nullptr, 0, blockIdx.x, blockIdx.y);
    } else if (z == 2) {
        if (blockIdx.y >= (TD * B_) / 128) return;
        mma_gemm_body(sAh, sAl, sBh, sBl, TD * B_, H_, E_,
                      esH, esL, WinH, WinL, eproj, nullptr, 0, blockIdx.x, blockIdx.y);
    } else {
        if (blockIdx.x >= 4 || blockIdx.y >= 4) return;
        sgemm_tr_body((float*)sAh, (float*)sBh, Wo, Win, WcombT,
                      blockIdx.x, blockIdx.y);
    }
}

// ---------------- fused prep: conversions + gather + h copy + bar reset -----
__device__ void tconv_body(const float* __restrict__ W, int K, int N, int row_off,
                           __nv_bfloat16* __restrict__ oh, __nv_bfloat16* __restrict__ ol,
                           int bxx, int byy, float* t /*32*33 smem*/)
{
    int tx = threadIdx.x & 31, ty = threadIdx.x >> 5;
    int n0 = bxx * 32, k0 = byy * 32;
    for (int ky = ty; ky < 32; ky += 8)
        t[ky * 33 + tx] = W[(size_t)(row_off + k0 + ky) * N + n0 + tx];
    __syncthreads();
    for (int ny = ty; ny < 32; ny += 8) {
        float v = t[tx * 33 + ny];
        __nv_bfloat16 h, l; bsplit(v, h, l);
        size_t o = (size_t)(n0 + ny) * K + k0 + tx;
        oh[o] = h; ol[o] = l;
    }
}

constexpr int SEG0 = (B_ * TE * 2 * H_) / 4 / 256;   // 8192: aconv enc (float4)
constexpr int SEG1 = SEG0 + 512;     // tconv Wk
constexpr int SEG2 = SEG1 + 512;     // tconv Wv
constexpr int SEG3 = SEG2 + 256;     // tconv Win(rows offset 512)
constexpr int SEG4 = SEG3 + 16000;   // tconv Wd
constexpr int SEG5 = SEG4 + 2048;    // gather
constexpr int SEG6 = SEG5 + 128;     // copy h
constexpr int PREP_BLOCKS = SEG6;

__global__ __launch_bounds__(256) void prep_all_kernel(
    const float* __restrict__ enc, const float* __restrict__ Wk,
    const float* __restrict__ Wv, const float* __restrict__ Win,
    const float* __restrict__ Wd, const int* __restrict__ x,
    const float* __restrict__ emb, const float* __restrict__ h0)
{
    __shared__ float t[32 * 33];
    int blk = blockIdx.x, tid = threadIdx.x;
    if (blk == 0 && tid == 0) g_bar = 0;      // barrier reset (deterministic)
    if (blk < SEG0) {
        int i = blk * 256 + tid;
        float4 v = ((const float4*)enc)[i];
        __nv_bfloat16 h0_, h1_, h2_, h3_, l0_, l1_, l2_, l3_;
        bsplit(v.x, h0_, l0_); bsplit(v.y, h1_, l1_);
        bsplit(v.z, h2_, l2_); bsplit(v.w, h3_, l3_);
        ((__nv_bfloat162*)g_enc_h)[2 * i]     = __nv_bfloat162(h0_, h1_);
        ((__nv_bfloat162*)g_enc_h)[2 * i + 1] = __nv_bfloat162(h2_, h3_);
        ((__nv_bfloat162*)g_enc_l)[2 * i]     = __nv_bfloat162(l0_, l1_);
        ((__nv_bfloat162*)g_enc_l)[2 * i + 1] = __nv_bfloat162(l2_, l3_);
    } else if (blk < SEG1) {
        int i = blk - SEG0;
        tconv_body(Wk, 2 * H_, H_, 0, g_Wkt_h, g_Wkt_l, i % 16, i / 16, t);
    } else if (blk < SEG2) {
        int i = blk - SEG1;
        tconv_body(Wv, 2 * H_, H_, 0, g_Wvt_h, g_Wvt_l, i % 16, i / 16, t);
    } else if (blk < SEG3) {
        int i = blk - SEG2;
        tconv_body(Win, H_, H_, 512, g_Wint_h, g_Wint_l, i % 16, i / 16, t);
    } else if (blk < SEG4) {
        int i = blk - SEG3;
        tconv_body(Wd, H_, V_, 0, g_Wdt_h, g_Wdt_l, i % 1000, i / 1000, t);
    } else if (blk < SEG5) {
        int r = blk - SEG4;
        int tt = r >> 5, b = r & 31;
        int tok = x[b * TD + tt];
        const float* src = emb + (size_t)tok * E_;
        for (int i = tid; i < E_; i += 256) {
            __nv_bfloat16 h, l; bsplit(src[i], h, l);
            g_eseq_h[(size_t)r * E_ + i] = h;
            g_eseq_l[(size_t)r * E_ + i] = l;
        }
    } else {
        int i = (blk - SEG5) * 256 + tid;
        g_hA[i] = h0[i];
    }
}

// ---------------- transpose Kh (b,s,h,d) -> Kh2 (b,h,d,s) --------------------
__global__ void transpose_k_kernel()
{
    __shared__ float t[32][33];
    int bh = blockIdx.x;
    int b = bh >> 3, h = bh & 7;
    int s0 = blockIdx.y * 32, d0 = blockIdx.z * 32;
    for (int yy = threadIdx.y; yy < 32; yy += 8)
        t[yy][threadIdx.x] = g_Kh[((size_t)(b * 256 + s0 + yy) * 8 + h) * 64 + d0 + threadIdx.x];
    __syncthreads();
    for (int yy = threadIdx.y; yy < 32; yy += 8)
        g_Kh2[((size_t)(bh) * 64 + d0 + yy) * 256 + s0 + threadIdx.x] = t[threadIdx.x][yy];
}

__global__ void copy_kernel(const float* __restrict__ src, float* __restrict__ dst, int n)
{
    int i = blockIdx.x * blockDim.x + threadIdx.x;
    if (i < n) dst[i] = src[i];
}

// =================== PERSISTENT SCAN KERNEL ==================================
// smem layout (floats):
constexpr int OFF_W   = 0;                    // 24576: w[l][k][24]  (24=pass*12+g*4+j)
constexpr int OFF_WC  = 24576;                // 2048:  wcomb slice [k][4j]
constexpr int OFF_BFT = 26624;                // 16896: bfT[512][33] (k-major, lane=b)
constexpr int OFF_GP  = 43520;                // 12288: gate partials (2 sets x 6144)
                                              //        (attention buffers alias here)
constexpr int OFF_MU  = 55808;                // 32
constexpr int OFF_RS  = 55840;                // 32
constexpr int OFF_HPV = 55872;                // 128
constexpr int SCAN_SMEM_FLOATS = 56000;       // 224000 B

__device__ __forceinline__ void grid_bar(int& epoch) {
    __syncthreads();
    epoch += NBLK;
    if (threadIdx.x == 0) {
        int* p = &g_bar;
        asm volatile("red.release.gpu.global.add.s32 [%0], 1;" :: "l"(p) : "memory");
        int v;
        do {
            asm volatile("ld.acquire.gpu.global.s32 %0, [%1];" : "=r"(v) : "l"(p) : "memory");
        } while (v < epoch);
    }
    __syncthreads();
}

__global__ __launch_bounds__(NTHR, 1) void scan_kernel(
    const float* __restrict__ Wq,  const int* __restrict__ vlen,
    const float* __restrict__ Wih, const float* __restrict__ Whh,
    const float* __restrict__ bih, const float* __restrict__ bhh,
    const float* __restrict__ lng, const float* __restrict__ lnb,
    const float* __restrict__ alph)
{
    extern __shared__ float sm[];
    float* w   = sm + OFF_W;
    float* wcs = sm + OFF_WC;
    float* bfT = sm + OFF_BFT;
    float* gp  = sm + OFF_GP;
    float* at  = sm + OFF_GP;   // attention buffers alias gp
    float* mu  = sm + OFF_MU;
    float* rs  = sm + OFF_RS;
    float* hpv = sm + OFF_HPV;

    const int tid = threadIdx.x, lane = tid & 31, wid = tid >> 5;
    const int blk = blockIdx.x;
    int epoch = 0;

    // ---- one-time weight staging ----
    // GRU weights: w[(l*512+k)*24 + pass*12 + g*4 + j]  (pass 0=ih, 1=hh)
    for (int i = tid; i < 24576; i += NTHR) {
        int unit = i >> 9, k = i & 511;           // coalesced over k
        int l = unit / 24, idx = unit % 24;
        int pass = idx / 12, r = idx % 12;
        int g = r >> 2, j = r & 3;
        const float* src = (pass == 0)
            ? (Wih + ((size_t)l * 1536 + g * 512 + blk * 4 + j) * 512)
            : (Whh + ((size_t)l * 1536 + g * 512 + blk * 4 + j) * 512);
        w[((l * 512 + k) * 24) + pass * 12 + g * 4 + j] = src[k];
    }
    // Wcomb slice: wcs[k*4+j] = Wcomb[k][blk*4+j] = g_Wcombt[(blk*4+j)*512+k]
    for (int i = tid; i < 2048; i += NTHR) {
        int k = i >> 2, j = i & 3;
        wcs[i] = g_Wcombt[(size_t)(blk * 4 + j) * 512 + k];
    }
    __syncthreads();

    for (int t = 0; t < TD; t++) {
        const float* hin  = (t & 1) ? g_hB : g_hA;
        float*       hout = (t & 1) ? g_hA : g_hB;

        // ================= phase 1: attention (2 bh-units per block) ========
        {
            int grp = tid >> 8, lt = tid & 255;
            int u = blk * 2 + grp;
            int b = u >> 3, h = u & 7;
            float* sh_ = at + grp * 1088;
            float* sq_ = sh_ + 512;
            float* sp_ = sq_ + 64;
            float* rd_ = sp_ + 256;
            const float* hlast = hin + (L_ - 1) * B_ * H_ + b * 512;

            sh_[lt] = hlast[lt];
            sh_[lt + 256] = hlast[lt + 256];
            __syncthreads();

            int d = lt & 63, c = lt >> 6;
            {
                float acc = 0.f;
                const float* wq = Wq + h * 64 + d;
#pragma unroll 8
                for (int k = c * 128; k < c * 128 + 128; k++)
                    acc += sh_[k] * wq[(size_t)k * 512];
                rd_[lt] = acc;
            }
            __syncthreads();
            if (lt < 64) sq_[lt] = rd_[lt] + rd_[lt + 64] + rd_[lt + 128] + rd_[lt + 192];
            __syncthreads();

            float sc = -1e6f;
            int vl = vlen[b];
            if (lt < vl) {
                float a = 0.f;
                const float* kp = g_Kh2 + (size_t)u * 64 * 256 + lt;
#pragma unroll 8
                for (int dd = 0; dd < 64; dd++) a += sq_[dd] * kp[dd * 256];
                sc = a * 0.125f;
            }
            int wg = lt >> 5;
            float m = sc;
#pragma unroll
            for (int o = 16; o; o >>= 1) m = fmaxf(m, __shfl_xor_sync(0xffffffffu, m, o));
            if ((lt & 31) == 0) rd_[wg] = m;
            __syncthreads();
            float mx = rd_[0];
#pragma unroll
            for (int i = 1; i < 8; i++) mx = fmaxf(mx, rd_[i]);
            float p = __expf(sc - mx);
            float s = p;
#pragma unroll
            for (int o = 16; o; o >>= 1) s += __shfl_xor_sync(0xffffffffu, s, o);
            if ((lt & 31) == 0) rd_[8 + wg] = s;
            __syncthreads();
            float sum = rd_[8];
#pragma unroll
            for (int i = 1; i < 8; i++) sum += rd_[8 + i];
            sp_[lt] = p / sum;
            __syncthreads();

            {
                float a = 0.f;
                const float* vp = g_Vh + ((size_t)(b * 256 + c * 64) * 8 + h) * 64 + d;
#pragma unroll 8
                for (int ss = 0; ss < 64; ss++) a += sp_[c * 64 + ss] * vp[(size_t)ss * 512];
                rd_[lt] = a;
            }
            __syncthreads();
            if (lt < 64)
                g_ctx[b * 512 + h * 64 + lt] =
                    rd_[lt] + rd_[lt + 64] + rd_[lt + 128] + rd_[lt + 192];
        }
        grid_bar(epoch);

        // ================= phase 2: xr = ctx @ Wcomb + eproj[t] =============
        // stage ctx transposed: bfT[k][b]
        for (int i = tid; i < 16384; i += NTHR) {
            int b = i >> 9, k = i & 511;
            bfT[k * 33 + b] = g_ctx[i];
        }
        __syncthreads();
        {
            int kc = wid * 32;
            float a0 = 0.f, a1 = 0.f, a2 = 0.f, a3 = 0.f;
#pragma unroll 4
            for (int kk = 0; kk < 32; kk++) {
                float xv = bfT[(kc + kk) * 33 + lane];
                float4 wv = *(const float4*)(wcs + (kc + kk) * 4);
                a0 += wv.x * xv; a1 += wv.y * xv; a2 += wv.z * xv; a3 += wv.w * xv;
            }
            gp[(wid * 4 + 0) * 32 + lane] = a0;
            gp[(wid * 4 + 1) * 32 + lane] = a1;
            gp[(wid * 4 + 2) * 32 + lane] = a2;
            gp[(wid * 4 + 3) * 32 + lane] = a3;
        }
        __syncthreads();
        if (tid < 128) {
            int j = tid >> 5, b = tid & 31, jg = blk * 4 + j;
            float v = 0.f;
#pragma unroll
            for (int w2 = 0; w2 < 16; w2++) v += gp[(w2 * 4 + j) * 32 + b];
            g_xra[b * 512 + jg] = v + g_eproj[(size_t)(t * B_ + b) * H_ + jg];
        }
        grid_bar(epoch);

        // ================= phases 3,4: GRU layers ===========================
        for (int l = 0; l < 2; l++) {
            const float* xr = (l == 0) ? g_xra : g_xrb;
            const float* hsrc = hin + l * B_ * H_;
            float* hdst = hout + l * B_ * H_;

            // stage h transposed
            for (int i = tid; i < 16384; i += NTHR) {
                int b = i >> 9, k = i & 511;
                bfT[k * 33 + b] = hsrc[i];
            }
            __syncthreads();
            if (tid < 128)
                hpv[tid] = bfT[(blk * 4 + (tid >> 5)) * 33 + (tid & 31)];
            // hh pass -> gp set 1
            {
                int kc = wid * 32;
                float acc[12];
#pragma unroll
                for (int i = 0; i < 12; i++) acc[i] = 0.f;
                const float* wrow = w + ((size_t)(l * 512 + kc) * 24) + 12;
#pragma unroll 4
                for (int kk = 0; kk < 32; kk++) {
                    float xv = bfT[(kc + kk) * 33 + lane];
                    float4 w0 = *(const float4*)(wrow + kk * 24 + 0);
                    float4 w1 = *(const float4*)(wrow + kk * 24 + 4);
                    float4 w2 = *(const float4*)(wrow + kk * 24 + 8);
                    acc[0] += w0.x * xv; acc[1] += w0.y * xv; acc[2] += w0.z * xv; acc[3] += w0.w * xv;
                    acc[4] += w1.x * xv; acc[5] += w1.y * xv; acc[6] += w1.z * xv; acc[7] += w1.w * xv;
                    acc[8] += w2.x * xv; acc[9] += w2.y * xv; acc[10] += w2.z * xv; acc[11] += w2.w * xv;
                }
#pragma unroll
                for (int i = 0; i < 12; i++)
                    gp[6144 + (wid * 12 + i) * 32 + lane] = acc[i];
            }
            __syncthreads();
            // stage xr transposed (raw)
            for (int i = tid; i < 16384; i += NTHR) {
                int b = i >> 9, k = i & 511;
                bfT[k * 33 + b] = xr[i];
            }
            __syncthreads();
            // LN stats from bfT (2 rows per warp)
            {
#pragma unroll
                for (int rr = 0; rr < 2; rr++) {
                    int b = wid * 2 + rr;
                    float s1 = 0.f, s2 = 0.f;
#pragma unroll
                    for (int kk = 0; kk < 16; kk++) {
                        float v = bfT[(lane + kk * 32) * 33 + b];
                        s1 += v; s2 += v * v;
                    }
#pragma unroll
                    for (int o = 16; o; o >>= 1) {
                        s1 += __shfl_xor_sync(0xffffffffu, s1, o);
                        s2 += __shfl_xor_sync(0xffffffffu, s2, o);
                    }
                    if (lane == 0) {
                        float m = s1 * (1.f / 512.f);
                        float var = s2 * (1.f / 512.f) - m * m;
                        mu[b] = m;
                        rs[b] = rsqrtf(var + 1e-5f);
                    }
                }
            }
            __syncthreads();
            // normalize bfT in place
            for (int i = tid; i < 16384; i += NTHR) {
                int b = i >> 9, k = i & 511;
                float gmm = lng[l * 512 + k], bta = lnb[l * 512 + k];
                bfT[k * 33 + b] = (bfT[k * 33 + b] - mu[b]) * rs[b] * gmm + bta;
            }
            __syncthreads();
            // ih pass -> gp set 0
            {
                int kc = wid * 32;
                float acc[12];
#pragma unroll
                for (int i = 0; i < 12; i++) acc[i] = 0.f;
                const float* wrow = w + ((size_t)(l * 512 + kc) * 24);
#pragma unroll 4
                for (int kk = 0; kk < 32; kk++) {
                    float xv = bfT[(kc + kk) * 33 + lane];
                    float4 w0 = *(const float4*)(wrow + kk * 24 + 0);
                    float4 w1 = *(const float4*)(wrow + kk * 24 + 4);
                    float4 w2 = *(const float4*)(wrow + kk * 24 + 8);
                    acc[0] += w0.x * xv; acc[1] += w0.y * xv; acc[2] += w0.z * xv; acc[3] += w0.w * xv;
                    acc[4] += w1.x * xv; acc[5] += w1.y * xv; acc[6] += w1.z * xv; acc[7] += w1.w * xv;
                    acc[8] += w2.x * xv; acc[9] += w2.y * xv; acc[10] += w2.z * xv; acc[11] += w2.w * xv;
                }
#pragma unroll
                for (int i = 0; i < 12; i++)
                    gp[(wid * 12 + i) * 32 + lane] = acc[i];
            }
            __syncthreads();
            // combine
            if (tid < 128) {
                int j = tid >> 5, b = tid & 31, jg = blk * 4 + j;
                float ir = 0.f, iz = 0.f, ig = 0.f, hr = 0.f, hz = 0.f, hg = 0.f;
#pragma unroll
                for (int w2 = 0; w2 < 16; w2++) {
                    const float* g0 = gp + (w2 * 12) * 32 + b;          // ih
                    const float* g1 = gp + 6144 + (w2 * 12) * 32 + b;   // hh
                    ir += g0[(0 * 4 + j) * 32];
                    iz += g0[(1 * 4 + j) * 32];
                    ig += g0[(2 * 4 + j) * 32];
                    hr += g1[(0 * 4 + j) * 32];
                    hz += g1[(1 * 4 + j) * 32];
                    hg += g1[(2 * 4 + j) * 32];
                }
                ir += bih[l * 1536 + jg];        hr += bhh[l * 1536 + jg];
                iz += bih[l * 1536 + 512 + jg];  hz += bhh[l * 1536 + 512 + jg];
                ig += bih[l * 1536 + 1024 + jg]; hg += bhh[l * 1536 + 1024 + jg];
                float r = fsig(ir + hr);
                float z = fsig(iz + hz);
                float g = ftanh(ig + r * hg);
                float hn = (1.f - z) * g + z * hpv[tid];
                hdst[b * 512 + jg] = hn;
                float yv = xr[b * 512 + jg] + alph[l] * hn;
                if (l == 0) {
                    g_xrb[b * 512 + jg] = yv;
                } else {
                    __nv_bfloat16 yh, yl; bsplit(yv, yh, yl);
                    size_t o = (size_t)(t * B_ + b) * 512 + jg;
                    g_ys_h[o] = yh;
                    g_ys_l[o] = yl;
                }
            }
            grid_bar(epoch);
        }
    }
}

// ============================ host orchestration ============================
extern "C" void kernel_launch(void* const* d_in, const int* in_sizes, int n_in,
                              void* d_out, int out_size)
{
    const int*   x    = (const int*)  d_in[0];
    const float* enc  = (const float*)d_in[1];
    const float* h0   = (const float*)d_in[2];
    const int*   vlen = (const int*)  d_in[3];
    const float* emb  = (const float*)d_in[4];
    const float* Wq   = (const float*)d_in[5];
    const float* Wk   = (const float*)d_in[6];
    const float* Wv   = (const float*)d_in[7];
    const float* Wo   = (const float*)d_in[8];
    const float* Win  = (const float*)d_in[9];
    const float* lng  = (const float*)d_in[10];
    const float* lnb  = (const float*)d_in[11];
    const float* alph = (const float*)d_in[12];
    const float* Wih  = (const float*)d_in[13];
    const float* Whh  = (const float*)d_in[14];
    const float* bih  = (const float*)d_in[15];
    const float* bhh  = (const float*)d_in[16];
    const float* Wd   = (const float*)d_in[17];
    const float* bd   = (const float*)d_in[18];
    float* out = (float*)d_out;

    cudaFuncSetAttribute(scan_kernel, cudaFuncAttributeMaxDynamicSharedMemorySize,
                         SCAN_SMEM_FLOATS * 4);

    float *pKh, *pVh, *pEproj, *pWcombT, *pHA;
    __nv_bfloat16 *pEncH, *pEncL, *pWktH, *pWktL, *pWvtH, *pWvtL, *pWintH, *pWintL;
    __nv_bfloat16 *pWdtH, *pWdtL, *pEsH, *pEsL, *pYsH, *pYsL;
    cudaGetSymbolAddress((void**)&pKh,     g_Kh);
    cudaGetSymbolAddress((void**)&pVh,     g_Vh);
    cudaGetSymbolAddress((void**)&pEproj,  g_eproj);
    cudaGetSymbolAddress((void**)&pWcombT, g_Wcombt);
    cudaGetSymbolAddress((void**)&pHA,     g_hA);
    cudaGetSymbolAddress((void**)&pEncH,   g_enc_h);
    cudaGetSymbolAddress((void**)&pEncL,   g_enc_l);
    cudaGetSymbolAddress((void**)&pWktH,   g_Wkt_h);
    cudaGetSymbolAddress((void**)&pWktL,   g_Wkt_l);
    cudaGetSymbolAddress((void**)&pWvtH,   g_Wvt_h);
    cudaGetSymbolAddress((void**)&pWvtL,   g_Wvt_l);
    cudaGetSymbolAddress((void**)&pWintH,  g_Wint_h);
    cudaGetSymbolAddress((void**)&pWintL,  g_Wint_l);
    cudaGetSymbolAddress((void**)&pWdtH,   g_Wdt_h);
    cudaGetSymbolAddress((void**)&pWdtL,   g_Wdt_l);
    cudaGetSymbolAddress((void**)&pEsH,    g_eseq_h);
    cudaGetSymbolAddress((void**)&pEsL,    g_eseq_l);
    cudaGetSymbolAddress((void**)&pYsH,    g_ys_h);
    cudaGetSymbolAddress((void**)&pYsL,    g_ys_l);

    // my launch 0: fused prep (conversions + gather + h copy + bar reset)
    prep_all_kernel<<<PREP_BLOCKS, 256>>>(enc, Wk, Wv, Win, Wd, x, emb, h0);

    // my launch 1: batched K/V/eproj HMMA + Wcomb^T sgemm (z=3)
    mma_batched_kernel<<<dim3(4, 64, 4), 256>>>(
        pEncH, pEncL, pWktH, pWktL, pWvtH, pWvtL,
        pEsH, pEsL, pWintH, pWintL, pKh, pVh, pEproj,
        Wo, Win, pWcombT);

    // my launch 2: Kh transpose
    transpose_k_kernel<<<dim3(B_ * NH, TE / 32, DH / 32), dim3(32, 8)>>>();

    // my launch 3 (ncu-profiled slot): the whole 64-step scan
    scan_kernel<<<NBLK, NTHR, SCAN_SMEM_FLOATS * 4>>>(
        Wq, vlen, Wih, Whh, bih, bhh, lng, lnb, alph);

    // my launch 4: logits (HMMA, pipelined), transposed write to (B,T,V)
    mma_gemm_kernel<<<dim3(V_ / 128, (TD * B_) / 128), 256>>>(
        TD * B_, V_, H_, pYsH, pYsL, pWdtH, pWdtL, out, bd, 1);

    // my launch 5: final hidden state (t=63 odd -> final state lives in g_hA)
    if (out_size >= BTV + LBH)
        copy_kernel<<<(LBH + 255) / 256, 256>>>(pHA, out + BTV, LBH);
}